// round 2
// baseline (speedup 1.0000x reference)
#include <cuda_runtime.h>

#define K 7
#define HH 1024
#define WW 1024
#define CHUNKS 8
#define NBLK (K * K * CHUNKS)

// scratch: per-(bin, chunk) partial sums + completion counter
__device__ float g_partial[NBLK];
__device__ unsigned int g_count;   // zero-initialized; finalizer resets to 0

__device__ __forceinline__ void bin_extents(float ci, float cj, float h, float w,
                                            int bi, int bj,
                                            int& r0, int& r1, int& c0, int& c1) {
    // Mirror the reference float32 arithmetic.
    float i0 = ci - h * 0.5f, i1 = ci + h * 0.5f;
    float j0 = cj - w * 0.5f, j1 = cj + w * 0.5f;
    float stepi = (i1 - i0) / (float)(K + 1);
    float stepj = (j1 - j0) / (float)(K + 1);
    float ic = i0 + (float)(bi + 1) * stepi;
    float jc = j0 + (float)(bj + 1) * stepj;
    float bh2 = h / (float)K * 0.5f;
    float bw2 = w / (float)K * 0.5f;
    r0 = (int)floorf((ic - bh2) * (float)HH);
    r1 = (int)ceilf ((ic + bh2) * (float)HH);
    c0 = (int)floorf((jc - bw2) * (float)WW);
    c1 = (int)ceilf ((jc + bw2) * (float)WW);
    r0 = max(r0, 0); r1 = min(r1, HH);
    c0 = max(c0, 0); c1 = min(c1, WW);
}

__global__ void psroi_fused_kernel(const float* __restrict__ x,
                                   const float* __restrict__ region,
                                   float* __restrict__ out) {
    const int blk   = blockIdx.x;          // 0..NBLK-1
    const int bin   = blk >> 3;            // 0..48
    const int chunk = blk & 7;             // 0..7
    const int bi = bin / K, bj = bin % K;
    const int t  = threadIdx.x;

    const float ci = region[0], cj = region[1];
    const float rh = region[2], rw = region[3];

    int r0, r1, c0, c1;
    bin_extents(ci, cj, rh, rw, bi, bj, r0, r1, c0, c1);

    const int nrows = r1 - r0;
    const int ncols = c1 - c0;
    const int rpc   = (nrows + CHUNKS - 1) / CHUNKS;   // rows per chunk
    const int cr0   = r0 + chunk * rpc;
    const int cr1   = min(r1, cr0 + rpc);
    const int crows = max(cr1 - cr0, 0);

    const float* __restrict__ chan = x + (size_t)bin * HH * WW;

    const int total = crows * ncols;
    float acc = 0.0f;
    // coalesced: consecutive threads -> consecutive cols
    for (int idx = t; idx < total; idx += blockDim.x) {
        int rr = idx / ncols;
        int cc = idx - rr * ncols;
        acc += __ldg(&chan[(size_t)(cr0 + rr) * WW + (c0 + cc)]);
    }

    // deterministic block tree-reduction
    __shared__ float s[128];
    s[t] = acc;
    __syncthreads();
    #pragma unroll
    for (int o = 64; o > 0; o >>= 1) {
        if (t < o) s[t] += s[t + o];
        __syncthreads();
    }

    // publish partial, then count arrivals; last block finalizes
    __shared__ bool is_last;
    if (t == 0) {
        g_partial[blk] = s[0];
        __threadfence();
        unsigned int prev = atomicAdd(&g_count, 1u);
        is_last = (prev == (unsigned int)(NBLK - 1));
    }
    __syncthreads();

    if (!is_last) return;

    // ---- finalize in the last-arriving block (deterministic order) ----
    float score = 0.0f;
    if (t < K * K) {
        int fbi = t / K, fbj = t % K;
        int fr0, fr1, fc0, fc1;
        bin_extents(ci, cj, rh, rw, fbi, fbj, fr0, fr1, fc0, fc1);
        float sum = 0.0f;
        #pragma unroll
        for (int c = 0; c < CHUNKS; c++)
            sum += *(volatile float*)&g_partial[t * CHUNKS + c];  // bypass L1
        float cnt = (float)((fr1 - fr0) * (fc1 - fc0));
        score = sum / cnt;
    }
    s[t] = (t < 64) ? ((t < K * K) ? score : 0.0f) : 0.0f;
    __syncthreads();
    if (t < 64) {
        #pragma unroll
        for (int o = 32; o > 0; o >>= 1) {
            if (t < o) s[t] += s[t + o];
            __syncthreads();
        }
    }
    if (t == 0) {
        out[0] = s[0] / (float)(K * K);
        __threadfence();
        g_count = 0;   // reset for next graph replay
    }
}

extern "C" void kernel_launch(void* const* d_in, const int* in_sizes, int n_in,
                              void* d_out, int out_size) {
    const float* x      = (const float*)d_in[0];
    const float* region = (const float*)d_in[1];
    float* out = (float*)d_out;

    psroi_fused_kernel<<<NBLK, 128>>>(x, region, out);
}